// round 9
// baseline (speedup 1.0000x reference)
#include <cuda_runtime.h>
#include <cstdint>

#define Bn  4
#define Sn  1024
#define DMn 1024
#define Hn  16
#define DKn 64

// Scratch (allocation-free rule: __device__ globals)
__device__ float g_Q[(size_t)Bn * Hn * Sn * DKn];   // [b,h,s,k]
__device__ float g_K[(size_t)Bn * Hn * Sn * DKn];
__device__ float g_V[(size_t)Bn * Hn * Sn * DKn];
__device__ float g_Z[(size_t)Bn * Sn * Hn * DKn];   // [b,s,h*64+v]
// Transposed (K-major) weights, tf32-rounded:
//   n in [0,1024): Q | [1024,2048): K | [2048,3072): V | [3072,4096): Wo col
__device__ float g_Wt[(size_t)4096 * 1024];

__device__ __forceinline__ float to_tf32(float x) {
    uint32_t u;
    asm("cvt.rna.tf32.f32 %0, %1;" : "=r"(u) : "f"(x));
    return __uint_as_float(u);
}
__device__ __forceinline__ uint32_t smem_u32(const void* p) {
    uint32_t a;
    asm("{ .reg .u64 t; cvta.to.shared.u64 t, %1; cvt.u32.u64 %0, t; }"
        : "=r"(a) : "l"(p));
    return a;
}
__device__ __forceinline__ void cp16(uint32_t dst, const void* src) {
    asm volatile("cp.async.cg.shared.global [%0], [%1], 16;"
                 :: "r"(dst), "l"(src));
}
__device__ __forceinline__ void cp_commit() {
    asm volatile("cp.async.commit_group;");
}
template <int N>
__device__ __forceinline__ void cp_wait() {
    asm volatile("cp.async.wait_group %0;" :: "n"(N));
}
__device__ __forceinline__ void ldsm_x4(uint32_t* r, uint32_t addr) {
    asm volatile("ldmatrix.sync.aligned.m8n8.x4.shared.b16 {%0,%1,%2,%3}, [%4];"
                 : "=r"(r[0]), "=r"(r[1]), "=r"(r[2]), "=r"(r[3]) : "r"(addr));
}
__device__ __forceinline__ void ldsm_x2(uint32_t* r, uint32_t addr) {
    asm volatile("ldmatrix.sync.aligned.m8n8.x2.shared.b16 {%0,%1}, [%2];"
                 : "=r"(r[0]), "=r"(r[1]) : "r"(addr));
}

__device__ __forceinline__ void mma_tf32(float* c, const uint32_t* a, const uint32_t* b) {
    asm volatile(
        "mma.sync.aligned.m16n8k8.row.col.f32.tf32.tf32.f32 "
        "{%0,%1,%2,%3}, {%4,%5,%6,%7}, {%8,%9}, {%0,%1,%2,%3};"
        : "+f"(c[0]), "+f"(c[1]), "+f"(c[2]), "+f"(c[3])
        : "r"(a[0]), "r"(a[1]), "r"(a[2]), "r"(a[3]), "r"(b[0]), "r"(b[1]));
}

// ---------------------------------------------------------------------------
// Kernel 0: pack weights transposed (K-major) + tf32-round.  grid=(128,32),256t
// ---------------------------------------------------------------------------
__global__ __launch_bounds__(256) void transpose_w_kernel(
    const float* __restrict__ Wq, const float* __restrict__ Wk,
    const float* __restrict__ Wv, const float* __restrict__ Wo)
{
    __shared__ float t[32][33];
    int n0 = blockIdx.x * 32;
    int d0 = blockIdx.y * 32;
    int r  = n0 >> 10;
    int tid = threadIdx.x;

    #pragma unroll
    for (int p = 0; p < 4; p++) {
        int idx = p * 256 + tid;
        int dl  = idx >> 5;
        int j   = idx & 31;
        int d   = d0 + dl;
        float v;
        if (r < 3) {
            int hh = (n0 >> 6) & 15;
            int k0 = n0 & 63;
            const float* W = (r == 0) ? Wq : (r == 1) ? Wk : Wv;
            v = W[(size_t)hh * 65536 + (size_t)d * 64 + k0 + j];
        } else {
            v = Wo[(size_t)d * 1024 + (n0 - 3072) + j];
        }
        t[dl][j] = v;
    }
    __syncthreads();
    #pragma unroll
    for (int p = 0; p < 4; p++) {
        int idx = p * 256 + tid;
        int nl  = idx >> 5;
        int dd  = idx & 31;
        g_Wt[(size_t)(n0 + nl) * 1024 + d0 + dd] = to_tf32(t[dd][nl]);
    }
}

// ---------------------------------------------------------------------------
// tf32 mma.sync GEMM, occupancy-optimized: tile BM=64 x BN=128, warp 32x32,
// 3 CTAs/SM (<=85 regs), 2-stage cp.async, ldmatrix fragment loads.
// ---------------------------------------------------------------------------
#define BKp 36
#define GEMM_STAGE ((64 + 128) * BKp)       // floats per stage (A+B)
#define GEMM_SMEM  (2 * GEMM_STAGE * 4)     // 55.3 KB

template <int MODE>
__global__ __launch_bounds__(256, 3) void gemm_mma_kernel(
    const float* __restrict__ Ain,
    const float* __restrict__ b0, const float* __restrict__ b1,
    const float* __restrict__ b2,
    const float* __restrict__ Xres, float* __restrict__ Out)
{
    extern __shared__ float smn[];
    const uint32_t s0 = smem_u32(smn);
    const uint32_t stageBytes = GEMM_STAGE * 4;
    const uint32_t bHalf = 64 * BKp * 4;    // B starts after A's 64 rows

    const int tid  = threadIdx.x;
    const int wid  = tid >> 5;
    const int lane = tid & 31;
    const int grp  = lane >> 2;
    const int tig  = lane & 3;
    const int wm   = wid & 1;     // 2 warp rows (32 M each)
    const int wn   = wid >> 1;    // 4 warp cols (32 N each)
    const int n0   = blockIdx.x * 128;
    const int m0   = blockIdx.y * 64;

    const float* A  = (MODE == 0) ? Ain : g_Z;
    const float* Bw = (MODE == 0) ? g_Wt : (g_Wt + (size_t)3072 * 1024);

    // Copy mapping: A = 512 16B-chunks (2/thread), B = 1024 (4/thread)
    const float* srcA[2];
    uint32_t dstA[2];
    #pragma unroll
    for (int i = 0; i < 2; i++) {
        int idx = i * 256 + tid;       // 0..511
        int row = idx >> 3;            // 0..63
        int c4  = idx & 7;
        srcA[i] = A + (size_t)(m0 + row) * 1024 + c4 * 4;
        dstA[i] = (uint32_t)(row * BKp + c4 * 4) * 4;
    }
    const float* srcB[4];
    uint32_t dstB[4];
    #pragma unroll
    for (int i = 0; i < 4; i++) {
        int idx = i * 256 + tid;       // 0..1023
        int row = idx >> 3;            // 0..127
        int c4  = idx & 7;
        srcB[i] = Bw + (size_t)(n0 + row) * 1024 + c4 * 4;
        dstB[i] = (uint32_t)(row * BKp + c4 * 4) * 4;
    }

    // ldmatrix lane address components
    const int laneRowA = ((lane >> 3) & 1) * 8 + (lane & 7);
    const int laneColA = (lane >> 4) * 4;
    const int laneRowB = lane & 7;
    const int laneColB = ((lane >> 3) & 1) * 4;
    uint32_t aLane[2], bLane[4];
    #pragma unroll
    for (int mt = 0; mt < 2; mt++)
        aLane[mt] = (uint32_t)((wm * 32 + mt * 16 + laneRowA) * BKp + laneColA) * 4;
    #pragma unroll
    for (int nt = 0; nt < 4; nt++)
        bLane[nt] = (uint32_t)((wn * 32 + nt * 8 + laneRowB) * BKp + laneColB) * 4;

    float acc[2][4][4];
    #pragma unroll
    for (int mt = 0; mt < 2; mt++)
        #pragma unroll
        for (int nt = 0; nt < 4; nt++)
            #pragma unroll
            for (int e = 0; e < 4; e++) acc[mt][nt][e] = 0.f;

    // Prologue: stage chunk 0 into buffer 0
    #pragma unroll
    for (int i = 0; i < 2; i++) cp16(s0 + dstA[i], srcA[i]);
    #pragma unroll
    for (int i = 0; i < 4; i++) cp16(s0 + bHalf + dstB[i], srcB[i]);
    cp_commit();

    for (int ch = 0; ch < 32; ch++) {
        cp_wait<0>();
        __syncthreads();   // chunk ch visible; all warps done with ch-1

        if (ch < 31) {
            uint32_t base = s0 + ((ch + 1) & 1) * stageBytes;
            int kt = (ch + 1) * 32;
            #pragma unroll
            for (int i = 0; i < 2; i++) cp16(base + dstA[i], srcA[i] + kt);
            #pragma unroll
            for (int i = 0; i < 4; i++) cp16(base + bHalf + dstB[i], srcB[i] + kt);
            cp_commit();
        }

        const uint32_t sAs = s0 + (ch & 1) * stageBytes;
        const uint32_t sBs = sAs + bHalf;

        #pragma unroll
        for (int ks = 0; ks < 4; ks++) {
            const uint32_t kOff = (uint32_t)(ks * 8) * 4;
            uint32_t bf[4][2];
            #pragma unroll
            for (int nt = 0; nt < 4; nt++)
                ldsm_x2(bf[nt], sBs + bLane[nt] + kOff);
            #pragma unroll
            for (int mt = 0; mt < 2; mt++) {
                uint32_t af[4];
                ldsm_x4(af, sAs + aLane[mt] + kOff);
                #pragma unroll
                for (int nt = 0; nt < 4; nt++)
                    mma_tf32(acc[mt][nt], af, bf[nt]);
            }
        }
    }

    // Epilogue: direct fragment stores
    #pragma unroll
    for (int nt = 0; nt < 4; nt++) {
        int n_base = n0 + wn * 32 + nt * 8;
        int ncol   = 2 * tig;
        if (MODE == 0) {
            int sel = n_base >> 10;
            int hh  = (n_base >> 6) & 15;
            int kk  = (n_base & 63) + ncol;
            const float* bias = (sel == 0) ? b0 : (sel == 1) ? b1 : b2;
            float* dst = (sel == 0) ? g_Q : (sel == 1) ? g_K : g_V;
            float bv0 = bias[hh * 64 + kk];
            float bv1 = bias[hh * 64 + kk + 1];
            #pragma unroll
            for (int mt = 0; mt < 2; mt++) {
                int r = m0 + wm * 32 + mt * 16 + grp;
                #pragma unroll
                for (int hrow = 0; hrow < 2; hrow++) {
                    int m  = r + hrow * 8;
                    int bb = m >> 10, ss = m & 1023;
                    float2 v;
                    v.x = acc[mt][nt][hrow * 2 + 0] + bv0;
                    v.y = acc[mt][nt][hrow * 2 + 1] + bv1;
                    *reinterpret_cast<float2*>(
                        &dst[((size_t)(bb * 16 + hh) * 1024 + ss) * 64 + kk]) = v;
                }
            }
        } else {
            int n  = n_base + ncol;
            float bv0 = b0[n], bv1 = b0[n + 1];
            #pragma unroll
            for (int mt = 0; mt < 2; mt++) {
                int r = m0 + wm * 32 + mt * 16 + grp;
                #pragma unroll
                for (int hrow = 0; hrow < 2; hrow++) {
                    int m = r + hrow * 8;
                    float2 xr = *reinterpret_cast<const float2*>(
                        &Xres[(size_t)m * 1024 + n]);
                    float2 v;
                    v.x = acc[mt][nt][hrow * 2 + 0] + bv0 + xr.x;
                    v.y = acc[mt][nt][hrow * 2 + 1] + bv1 + xr.y;
                    *reinterpret_cast<float2*>(&Out[(size_t)m * 1024 + n]) = v;
                }
            }
        }
    }
}

// ---------------------------------------------------------------------------
// Kernel 2: flash attention (unchanged from R8, proven).
// ---------------------------------------------------------------------------
#define AStr 68
#define ATTN_SMEM ((128 + 4 * 64) * AStr * 4)

__global__ __launch_bounds__(256, 2) void attn_mma_kernel()
{
    extern __shared__ float sm[];
    float* Ps    = sm;
    float* KsBuf = sm + 128 * AStr;
    float* VsBuf = KsBuf + 2 * 64 * AStr;
    const uint32_t sPs = smem_u32(Ps);
    const uint32_t sK0 = smem_u32(KsBuf);
    const uint32_t sV0 = smem_u32(VsBuf);
    const uint32_t tileBytes = 64 * AStr * 4;

    const int q0 = blockIdx.x * 128;
    const int h  = blockIdx.y;
    const int b  = blockIdx.z;
    const int bh = b * Hn + h;

    const float* Qg = g_Q + (size_t)bh * Sn * DKn;
    const float* Kg = g_K + (size_t)bh * Sn * DKn;
    const float* Vg = g_V + (size_t)bh * Sn * DKn;

    const int tid  = threadIdx.x;
    const int wid  = tid >> 5;
    const int lane = tid & 31;
    const int grp  = lane >> 2;
    const int tig  = lane & 3;
    const int r0   = wid * 16;

    const int laneRowA = ((lane >> 3) & 1) * 8 + (lane & 7);
    const int laneColA = (lane >> 4) * 4;
    const int laneRowB = lane & 7;
    const int laneColB = ((lane >> 3) & 1) * 4;
    const uint32_t pLane = (uint32_t)((r0 + laneRowA) * AStr + laneColA) * 4;
    uint32_t kLane[8];
    #pragma unroll
    for (int nt = 0; nt < 8; nt++)
        kLane[nt] = (uint32_t)((nt * 8 + laneRowB) * AStr + laneColB) * 4;

    const float* srcK[4];
    const float* srcV[4];
    uint32_t dstKV[4];
    #pragma unroll
    for (int i = 0; i < 4; i++) {
        int idx = i * 256 + tid;
        int row = idx >> 4;
        int c4  = idx & 15;
        srcK[i] = Kg + (size_t)row * DKn + c4 * 4;
        srcV[i] = Vg + (size_t)row * DKn + c4 * 4;
        dstKV[i] = (uint32_t)(row * AStr + c4 * 4) * 4;
    }

    #pragma unroll
    for (int i = 0; i < 4; i++) {
        cp16(sK0 + dstKV[i], srcK[i]);
        cp16(sV0 + dstKV[i], srcV[i]);
    }
    cp_commit();

    #pragma unroll
    for (int it = 0; it < 8; it++) {
        int idx = it * 256 + tid;
        int row = idx >> 4;
        int c4  = idx & 15;
        float4 v = *reinterpret_cast<const float4*>(
            &Qg[(size_t)(q0 + row) * DKn + c4 * 4]);
        v.x *= 0.125f; v.y *= 0.125f; v.z *= 0.125f; v.w *= 0.125f;
        *reinterpret_cast<float4*>(&Ps[row * AStr + c4 * 4]) = v;
    }
    __syncthreads();

    uint32_t qf[8][4];
    #pragma unroll
    for (int kk = 0; kk < 8; kk++)
        ldsm_x4(qf[kk], sPs + pLane + (uint32_t)(kk * 8) * 4);

    float m_i[2] = {-3.0e38f, -3.0e38f};
    float l_i[2] = {0.f, 0.f};
    float o[8][4];
    #pragma unroll
    for (int nt = 0; nt < 8; nt++)
        #pragma unroll
        for (int e = 0; e < 4; e++) o[nt][e] = 0.f;

    for (int ti = 0; ti < 16; ti++) {
        cp_wait<0>();
        __syncthreads();

        if (ti < 15) {
            int off = (ti + 1) * 64 * DKn;
            uint32_t boff = ((ti + 1) & 1) * tileBytes;
            #pragma unroll
            for (int i = 0; i < 4; i++) {
                cp16(sK0 + boff + dstKV[i], srcK[i] + off);
                cp16(sV0 + boff + dstKV[i], srcV[i] + off);
            }
            cp_commit();
        }

        const uint32_t sKs = sK0 + (ti & 1) * tileBytes;
        const float* Vs = VsBuf + (ti & 1) * 64 * AStr;

        float s[8][4];
        #pragma unroll
        for (int nt = 0; nt < 8; nt++)
            #pragma unroll
            for (int e = 0; e < 4; e++) s[nt][e] = 0.f;

        #pragma unroll
        for (int kk = 0; kk < 8; kk++) {
            const uint32_t kOff = (uint32_t)(kk * 8) * 4;
            #pragma unroll
            for (int nt = 0; nt < 8; nt++) {
                uint32_t bf[2];
                ldsm_x2(bf, sKs + kLane[nt] + kOff);
                mma_tf32(s[nt], qf[kk], bf);
            }
        }

        float rm0 = -3.0e38f, rm1 = -3.0e38f;
        #pragma unroll
        for (int nt = 0; nt < 8; nt++) {
            rm0 = fmaxf(rm0, fmaxf(s[nt][0], s[nt][1]));
            rm1 = fmaxf(rm1, fmaxf(s[nt][2], s[nt][3]));
        }
        rm0 = fmaxf(rm0, __shfl_xor_sync(0xffffffffu, rm0, 1));
        rm0 = fmaxf(rm0, __shfl_xor_sync(0xffffffffu, rm0, 2));
        rm1 = fmaxf(rm1, __shfl_xor_sync(0xffffffffu, rm1, 1));
        rm1 = fmaxf(rm1, __shfl_xor_sync(0xffffffffu, rm1, 2));

        float nm0 = fmaxf(m_i[0], rm0);
        float nm1 = fmaxf(m_i[1], rm1);
        float corr0 = __expf(m_i[0] - nm0);
        float corr1 = __expf(m_i[1] - nm1);
        m_i[0] = nm0; m_i[1] = nm1;

        float rs0 = 0.f, rs1 = 0.f;
        #pragma unroll
        for (int nt = 0; nt < 8; nt++) {
            s[nt][0] = __expf(s[nt][0] - nm0);
            s[nt][1] = __expf(s[nt][1] - nm0);
            s[nt][2] = __expf(s[nt][2] - nm1);
            s[nt][3] = __expf(s[nt][3] - nm1);
            rs0 += s[nt][0] + s[nt][1];
            rs1 += s[nt][2] + s[nt][3];
        }
        rs0 += __shfl_xor_sync(0xffffffffu, rs0, 1);
        rs0 += __shfl_xor_sync(0xffffffffu, rs0, 2);
        rs1 += __shfl_xor_sync(0xffffffffu, rs1, 1);
        rs1 += __shfl_xor_sync(0xffffffffu, rs1, 2);
        l_i[0] = l_i[0] * corr0 + rs0;
        l_i[1] = l_i[1] * corr1 + rs1;

        #pragma unroll
        for (int nt = 0; nt < 8; nt++) {
            o[nt][0] *= corr0; o[nt][1] *= corr0;
            o[nt][2] *= corr1; o[nt][3] *= corr1;
        }

        #pragma unroll
        for (int nt = 0; nt < 8; nt++) {
            *reinterpret_cast<float2*>(
                &Ps[(r0 + grp) * AStr + nt * 8 + 2 * tig]) =
                make_float2(s[nt][0], s[nt][1]);
            *reinterpret_cast<float2*>(
                &Ps[(r0 + grp + 8) * AStr + nt * 8 + 2 * tig]) =
                make_float2(s[nt][2], s[nt][3]);
        }
        __syncwarp();

        #pragma unroll
        for (int kk = 0; kk < 8; kk++) {
            int k = kk * 8;
            uint32_t af[4];
            ldsm_x4(af, sPs + pLane + (uint32_t)k * 4);
            #pragma unroll
            for (int nt = 0; nt < 8; nt++) {
                uint32_t bf[2];
                bf[0] = __float_as_uint(Vs[(k + tig)     * AStr + nt * 8 + grp]);
                bf[1] = __float_as_uint(Vs[(k + tig + 4) * AStr + nt * 8 + grp]);
                mma_tf32(o[nt], af, bf);
            }
        }
    }

    float inv0 = 1.0f / l_i[0];
    float inv1 = 1.0f / l_i[1];
    int row0 = q0 + r0 + grp;
    #pragma unroll
    for (int nt = 0; nt < 8; nt++) {
        int col = h * 64 + nt * 8 + 2 * tig;
        *reinterpret_cast<float2*>(
            &g_Z[((size_t)b * Sn + row0) * 1024 + col]) =
            make_float2(o[nt][0] * inv0, o[nt][1] * inv0);
        *reinterpret_cast<float2*>(
            &g_Z[((size_t)b * Sn + row0 + 8) * 1024 + col]) =
            make_float2(o[nt][2] * inv1, o[nt][3] * inv1);
    }
}

// ---------------------------------------------------------------------------
extern "C" void kernel_launch(void* const* d_in, const int* in_sizes, int n_in,
                              void* d_out, int out_size)
{
    const float* X  = (const float*)d_in[0];
    const float* Wk = (const float*)d_in[1];
    const float* bk = (const float*)d_in[2];
    const float* Wq = (const float*)d_in[3];
    const float* bq = (const float*)d_in[4];
    const float* Wv = (const float*)d_in[5];
    const float* bv = (const float*)d_in[6];
    const float* Wo = (const float*)d_in[7];
    const float* bo = (const float*)d_in[8];
    float* out = (float*)d_out;

    cudaFuncSetAttribute(gemm_mma_kernel<0>,
                         cudaFuncAttributeMaxDynamicSharedMemorySize, GEMM_SMEM);
    cudaFuncSetAttribute(gemm_mma_kernel<1>,
                         cudaFuncAttributeMaxDynamicSharedMemorySize, GEMM_SMEM);
    cudaFuncSetAttribute(attn_mma_kernel,
                         cudaFuncAttributeMaxDynamicSharedMemorySize, ATTN_SMEM);

    transpose_w_kernel<<<dim3(128, 32), 256>>>(Wq, Wk, Wv, Wo);
    gemm_mma_kernel<0><<<dim3(24, 64), 256, GEMM_SMEM>>>(
        X, bq, bk, bv, nullptr, nullptr);
    attn_mma_kernel<<<dim3(Sn / 128, Hn, Bn), 256, ATTN_SMEM>>>();
    gemm_mma_kernel<1><<<dim3(8, 64), 256, GEMM_SMEM>>>(
        nullptr, bo, nullptr, nullptr, X, out);
}

// round 10
// speedup vs baseline: 1.9080x; 1.9080x over previous
#include <cuda_runtime.h>
#include <cuda_fp16.h>
#include <cstdint>

#define Bn  4
#define Sn  1024
#define DMn 1024
#define Hn  16
#define DKn 64

// Scratch (allocation-free rule: __device__ globals). All half.
__device__ __half g_Xh[(size_t)Bn * Sn * DMn];        // X in half
__device__ __half g_Qh[(size_t)Bn * Hn * Sn * DKn];   // pre-scaled by 0.125
__device__ __half g_Kh[(size_t)Bn * Hn * Sn * DKn];
__device__ __half g_Vh[(size_t)Bn * Hn * Sn * DKn];
__device__ __half g_Zh[(size_t)Bn * Sn * Hn * DKn];   // [b,s,h*64+v]
// K-major half weights: rows n, cols d.
//   n in [0,1024): Q | [1024,2048): K | [2048,3072): V | [3072,4096): Wo col
__device__ __half g_Wth[(size_t)4096 * 1024];

__device__ __forceinline__ uint32_t smem_u32(const void* p) {
    uint32_t a;
    asm("{ .reg .u64 t; cvta.to.shared.u64 t, %1; cvt.u32.u64 %0, t; }"
        : "=r"(a) : "l"(p));
    return a;
}
__device__ __forceinline__ void cp16(uint32_t dst, const void* src) {
    asm volatile("cp.async.cg.shared.global [%0], [%1], 16;"
                 :: "r"(dst), "l"(src));
}
__device__ __forceinline__ void cp_commit() {
    asm volatile("cp.async.commit_group;");
}
template <int N>
__device__ __forceinline__ void cp_wait() {
    asm volatile("cp.async.wait_group %0;" :: "n"(N));
}
__device__ __forceinline__ void ldsm_x4(uint32_t* r, uint32_t addr) {
    asm volatile("ldmatrix.sync.aligned.m8n8.x4.shared.b16 {%0,%1,%2,%3}, [%4];"
                 : "=r"(r[0]), "=r"(r[1]), "=r"(r[2]), "=r"(r[3]) : "r"(addr));
}
__device__ __forceinline__ void ldsm_x2(uint32_t* r, uint32_t addr) {
    asm volatile("ldmatrix.sync.aligned.m8n8.x2.shared.b16 {%0,%1}, [%2];"
                 : "=r"(r[0]), "=r"(r[1]) : "r"(addr));
}
__device__ __forceinline__ void ldsm_x2t(uint32_t* r, uint32_t addr) {
    asm volatile("ldmatrix.sync.aligned.m8n8.x2.trans.shared.b16 {%0,%1}, [%2];"
                 : "=r"(r[0]), "=r"(r[1]) : "r"(addr));
}

// fp16 mma: m16n8k16, f32 accumulate. Same reg shape as tf32 m16n8k8, 2x K.
__device__ __forceinline__ void mma_f16(float* c, const uint32_t* a, const uint32_t* b) {
    asm volatile(
        "mma.sync.aligned.m16n8k16.row.col.f32.f16.f16.f32 "
        "{%0,%1,%2,%3}, {%4,%5,%6,%7}, {%8,%9}, {%0,%1,%2,%3};"
        : "+f"(c[0]), "+f"(c[1]), "+f"(c[2]), "+f"(c[3])
        : "r"(a[0]), "r"(a[1]), "r"(a[2]), "r"(a[3]), "r"(b[0]), "r"(b[1]));
}

// ---------------------------------------------------------------------------
// Kernel A: X -> half.  grid=2048, block=256, 8 elems/thread.
// ---------------------------------------------------------------------------
__global__ __launch_bounds__(256) void x2h_kernel(const float* __restrict__ X)
{
    size_t base = ((size_t)blockIdx.x * 256 + threadIdx.x) * 8;
    #pragma unroll
    for (int j = 0; j < 4; j++) {
        float2 v = *reinterpret_cast<const float2*>(&X[base + j * 2]);
        *reinterpret_cast<__half2*>(&g_Xh[base + j * 2]) = __floats2half2_rn(v.x, v.y);
    }
}

// ---------------------------------------------------------------------------
// Kernel 0: pack weights transposed (K-major) into half.  grid=(128,32),256t
// ---------------------------------------------------------------------------
__global__ __launch_bounds__(256) void transpose_w_kernel(
    const float* __restrict__ Wq, const float* __restrict__ Wk,
    const float* __restrict__ Wv, const float* __restrict__ Wo)
{
    __shared__ float t[32][33];
    int n0 = blockIdx.x * 32;
    int d0 = blockIdx.y * 32;
    int r  = n0 >> 10;
    int tid = threadIdx.x;

    #pragma unroll
    for (int p = 0; p < 4; p++) {
        int idx = p * 256 + tid;
        int dl  = idx >> 5;
        int j   = idx & 31;
        int d   = d0 + dl;
        float v;
        if (r < 3) {
            int hh = (n0 >> 6) & 15;
            int k0 = n0 & 63;
            const float* W = (r == 0) ? Wq : (r == 1) ? Wk : Wv;
            v = W[(size_t)hh * 65536 + (size_t)d * 64 + k0 + j];
        } else {
            v = Wo[(size_t)d * 1024 + (n0 - 3072) + j];
        }
        t[dl][j] = v;
    }
    __syncthreads();
    #pragma unroll
    for (int p = 0; p < 4; p++) {
        int idx = p * 256 + tid;
        int nl  = idx >> 5;
        int dd  = idx & 31;
        g_Wth[(size_t)(n0 + nl) * 1024 + d0 + dd] = __float2half_rn(t[dd][nl]);
    }
}

// ---------------------------------------------------------------------------
// fp16 mma GEMM: BM=128, BN=128, K-chunk=64 halves, 16 chunks, 3-stage ring.
// ---------------------------------------------------------------------------
#define HStr 72                              // halves per smem row (64+8 pad)
#define GEMM_STAGE_B ((128 + 128) * HStr * 2)  // bytes per stage
#define GEMM_SMEM    (3 * GEMM_STAGE_B)        // 110.6 KB

template <int MODE>
__global__ __launch_bounds__(256, 2) void gemm_mma_kernel(
    const float* __restrict__ b0, const float* __restrict__ b1,
    const float* __restrict__ b2,
    const float* __restrict__ Xres, float* __restrict__ Out)
{
    extern __shared__ __half smh[];
    const uint32_t s0 = smem_u32(smh);
    const uint32_t bHalfOff = 128 * HStr * 2;   // B region after A's 128 rows

    const int tid  = threadIdx.x;
    const int wid  = tid >> 5;
    const int lane = tid & 31;
    const int grp  = lane >> 2;
    const int tig  = lane & 3;
    const int wm   = wid & 1;
    const int wn   = wid >> 1;
    const int n0   = blockIdx.x * 128;
    const int m0   = blockIdx.y * 128;

    const __half* A  = (MODE == 0) ? g_Xh : g_Zh;
    const __half* Bw = (MODE == 0) ? g_Wth : (g_Wth + (size_t)3072 * 1024);

    // Copy mapping per stage: A 1024 x 16B (4/thread), B same
    const __half* srcA[4];
    const __half* srcB[4];
    uint32_t dstOff[4];
    #pragma unroll
    for (int i = 0; i < 4; i++) {
        int idx = i * 256 + tid;       // 0..1023
        int row = idx >> 3;            // 0..127
        int c8  = idx & 7;             // 8 halves per 16B chunk
        srcA[i] = A  + (size_t)(m0 + row) * 1024 + c8 * 8;
        srcB[i] = Bw + (size_t)(n0 + row) * 1024 + c8 * 8;
        dstOff[i] = (uint32_t)(row * HStr + c8 * 8) * 2;
    }

    // ldmatrix lane addresses (half units)
    const int laneRowA = ((lane >> 3) & 1) * 8 + (lane & 7);
    const int laneColA = (lane >> 4) * 8;
    const int laneRowB = lane & 7;
    const int laneColB = ((lane >> 3) & 1) * 8;
    uint32_t aLane[4], bLane[4];
    #pragma unroll
    for (int mt = 0; mt < 4; mt++)
        aLane[mt] = (uint32_t)((wm * 64 + mt * 16 + laneRowA) * HStr + laneColA) * 2;
    #pragma unroll
    for (int nt = 0; nt < 4; nt++)
        bLane[nt] = (uint32_t)((wn * 32 + nt * 8 + laneRowB) * HStr + laneColB) * 2;

    float acc[4][4][4];
    #pragma unroll
    for (int mt = 0; mt < 4; mt++)
        #pragma unroll
        for (int nt = 0; nt < 4; nt++)
            #pragma unroll
            for (int e = 0; e < 4; e++) acc[mt][nt][e] = 0.f;

    // Prologue: stage chunks 0, 1
    #pragma unroll
    for (int st = 0; st < 2; st++) {
        uint32_t base = s0 + st * GEMM_STAGE_B;
        int kt = st * 64;
        #pragma unroll
        for (int i = 0; i < 4; i++) {
            cp16(base + dstOff[i], srcA[i] + kt);
            cp16(base + bHalfOff + dstOff[i], srcB[i] + kt);
        }
        cp_commit();
    }

    int stC = 0;
    for (int ch = 0; ch < 16; ch++) {
        if (ch < 15) cp_wait<1>(); else cp_wait<0>();
        __syncthreads();

        if (ch < 14) {
            int stN = stC + 2; if (stN >= 3) stN -= 3;
            uint32_t base = s0 + stN * GEMM_STAGE_B;
            int kt = (ch + 2) * 64;
            #pragma unroll
            for (int i = 0; i < 4; i++) {
                cp16(base + dstOff[i], srcA[i] + kt);
                cp16(base + bHalfOff + dstOff[i], srcB[i] + kt);
            }
            cp_commit();
        }

        const uint32_t sAs = s0 + stC * GEMM_STAGE_B;
        const uint32_t sBs = sAs + bHalfOff;

        #pragma unroll
        for (int ks = 0; ks < 4; ks++) {             // K=16 per step
            const uint32_t kOff = (uint32_t)(ks * 16) * 2;
            uint32_t bf[4][2];
            #pragma unroll
            for (int nt = 0; nt < 4; nt++)
                ldsm_x2(bf[nt], sBs + bLane[nt] + kOff);
            #pragma unroll
            for (int mt = 0; mt < 4; mt++) {
                uint32_t af[4];
                ldsm_x4(af, sAs + aLane[mt] + kOff);
                #pragma unroll
                for (int nt = 0; nt < 4; nt++)
                    mma_f16(acc[mt][nt], af, bf[nt]);
            }
        }
        if (++stC >= 3) stC = 0;
    }

    // Epilogue
    #pragma unroll
    for (int nt = 0; nt < 4; nt++) {
        int n_base = n0 + wn * 32 + nt * 8;
        int ncol   = 2 * tig;
        if (MODE == 0) {
            int sel = n_base >> 10;
            int hh  = (n_base >> 6) & 15;
            int kk  = (n_base & 63) + ncol;
            const float* bias = (sel == 0) ? b0 : (sel == 1) ? b1 : b2;
            __half* dst = (sel == 0) ? g_Qh : (sel == 1) ? g_Kh : g_Vh;
            float scale = (sel == 0) ? 0.125f : 1.0f;   // fold 1/sqrt(d) into Q
            float bv0 = bias[hh * 64 + kk];
            float bv1 = bias[hh * 64 + kk + 1];
            #pragma unroll
            for (int mt = 0; mt < 4; mt++) {
                int r = m0 + wm * 64 + mt * 16 + grp;
                #pragma unroll
                for (int hrow = 0; hrow < 2; hrow++) {
                    int m  = r + hrow * 8;
                    int bb = m >> 10, ss = m & 1023;
                    float v0 = (acc[mt][nt][hrow * 2 + 0] + bv0) * scale;
                    float v1 = (acc[mt][nt][hrow * 2 + 1] + bv1) * scale;
                    *reinterpret_cast<__half2*>(
                        &dst[((size_t)(bb * 16 + hh) * 1024 + ss) * 64 + kk]) =
                        __floats2half2_rn(v0, v1);
                }
            }
        } else {
            int n  = n_base + ncol;
            float bv0 = b0[n], bv1 = b0[n + 1];
            #pragma unroll
            for (int mt = 0; mt < 4; mt++) {
                int r = m0 + wm * 64 + mt * 16 + grp;
                #pragma unroll
                for (int hrow = 0; hrow < 2; hrow++) {
                    int m = r + hrow * 8;
                    float2 xr = *reinterpret_cast<const float2*>(
                        &Xres[(size_t)m * 1024 + n]);
                    float2 v;
                    v.x = acc[mt][nt][hrow * 2 + 0] + bv0 + xr.x;
                    v.y = acc[mt][nt][hrow * 2 + 1] + bv1 + xr.y;
                    *reinterpret_cast<float2*>(&Out[(size_t)m * 1024 + n]) = v;
                }
            }
        }
    }
}

// ---------------------------------------------------------------------------
// Kernel 2: flash attention, fp16 mma (K=16), ldmatrix for K, P, and V(.trans).
// grid = (S/128, H, B), block 256 (8 warps). Warp owns 16 full q-rows.
// ---------------------------------------------------------------------------
#define ATTN_SMEM ((128 + 2 * 64 + 2 * 64) * HStr * 2)   // 55.3 KB

__global__ __launch_bounds__(256, 2) void attn_mma_kernel()
{
    extern __shared__ __half smh[];
    __half* Ps    = smh;                       // 128 x 72 (Q staging, then P)
    __half* KsBuf = smh + 128 * HStr;          // 2 x 64 x 72
    __half* VsBuf = KsBuf + 2 * 64 * HStr;     // 2 x 64 x 72
    const uint32_t sPs = smem_u32(Ps);
    const uint32_t sK0 = smem_u32(KsBuf);
    const uint32_t sV0 = smem_u32(VsBuf);
    const uint32_t tileBytes = 64 * HStr * 2;

    const int q0 = blockIdx.x * 128;
    const int h  = blockIdx.y;
    const int b  = blockIdx.z;
    const int bh = b * Hn + h;

    const __half* Qg = g_Qh + (size_t)bh * Sn * DKn;
    const __half* Kg = g_Kh + (size_t)bh * Sn * DKn;
    const __half* Vg = g_Vh + (size_t)bh * Sn * DKn;

    const int tid  = threadIdx.x;
    const int wid  = tid >> 5;
    const int lane = tid & 31;
    const int grp  = lane >> 2;
    const int tig  = lane & 3;
    const int r0   = wid * 16;

    // ldmatrix lane addresses
    const int laneRowA = ((lane >> 3) & 1) * 8 + (lane & 7);
    const int laneColA = (lane >> 4) * 8;
    const uint32_t pLane = (uint32_t)((r0 + laneRowA) * HStr + laneColA) * 2;
    uint32_t kLane[8];
    #pragma unroll
    for (int nt = 0; nt < 8; nt++)
        kLane[nt] = (uint32_t)((nt * 8 + (lane & 7)) * HStr +
                               ((lane >> 3) & 1) * 8) * 2;
    const uint32_t vLane = (uint32_t)((lane & 15) * HStr) * 2;   // + nt*8*2 + kk*16*HStr*2

    // K/V copy mapping: 64 rows x 64 halves = 512 x 16B, 2/thread each
    const __half* srcK[2];
    const __half* srcV[2];
    uint32_t dstKV[2];
    #pragma unroll
    for (int i = 0; i < 2; i++) {
        int idx = i * 256 + tid;       // 0..511
        int row = idx >> 3;            // 0..63
        int c8  = idx & 7;
        srcK[i] = Kg + (size_t)row * DKn + c8 * 8;
        srcV[i] = Vg + (size_t)row * DKn + c8 * 8;
        dstKV[i] = (uint32_t)(row * HStr + c8 * 8) * 2;
    }
    // Q copy: 128 rows x 64 halves = 1024 x 16B, 4/thread
    const __half* srcQ[4];
    uint32_t dstQ[4];
    #pragma unroll
    for (int i = 0; i < 4; i++) {
        int idx = i * 256 + tid;
        int row = idx >> 3;            // 0..127
        int c8  = idx & 7;
        srcQ[i] = Qg + (size_t)(q0 + row) * DKn + c8 * 8;
        dstQ[i] = (uint32_t)(row * HStr + c8 * 8) * 2;
    }

    // Prologue: stage K/V tile 0 and Q
    #pragma unroll
    for (int i = 0; i < 2; i++) {
        cp16(sK0 + dstKV[i], srcK[i]);
        cp16(sV0 + dstKV[i], srcV[i]);
    }
    #pragma unroll
    for (int i = 0; i < 4; i++) cp16(sPs + dstQ[i], srcQ[i]);
    cp_commit();
    cp_wait<0>();
    __syncthreads();

    // Q fragments (pre-scaled by 0.125 at projection time)
    uint32_t qf[4][4];
    #pragma unroll
    for (int kk = 0; kk < 4; kk++)
        ldsm_x4(qf[kk], sPs + pLane + (uint32_t)(kk * 16) * 2);

    float m_i[2] = {-3.0e38f, -3.0e38f};
    float l_i[2] = {0.f, 0.f};
    float o[8][4];
    #pragma unroll
    for (int nt = 0; nt < 8; nt++)
        #pragma unroll
        for (int e = 0; e < 4; e++) o[nt][e] = 0.f;

    for (int ti = 0; ti < 16; ti++) {
        cp_wait<0>();
        __syncthreads();   // tile ti visible; all warps done with ti-1 (and qf)

        if (ti < 15) {
            int off = (ti + 1) * 64 * DKn;
            uint32_t boff = ((ti + 1) & 1) * tileBytes;
            #pragma unroll
            for (int i = 0; i < 2; i++) {
                cp16(sK0 + boff + dstKV[i], srcK[i] + off);
                cp16(sV0 + boff + dstKV[i], srcV[i] + off);
            }
            cp_commit();
        }

        const uint32_t sKs = sK0 + (ti & 1) * tileBytes;
        const uint32_t sVs = sV0 + (ti & 1) * tileBytes;

        // S = (Q/8) K^T : 4 kk-steps of K=16
        float s[8][4];
        #pragma unroll
        for (int nt = 0; nt < 8; nt++)
            #pragma unroll
            for (int e = 0; e < 4; e++) s[nt][e] = 0.f;

        #pragma unroll
        for (int kk = 0; kk < 4; kk++) {
            const uint32_t kOff = (uint32_t)(kk * 16) * 2;
            #pragma unroll
            for (int nt = 0; nt < 8; nt++) {
                uint32_t bf[2];
                ldsm_x2(bf, sKs + kLane[nt] + kOff);
                mma_f16(s[nt], qf[kk], bf);
            }
        }

        // Online softmax
        float rm0 = -3.0e38f, rm1 = -3.0e38f;
        #pragma unroll
        for (int nt = 0; nt < 8; nt++) {
            rm0 = fmaxf(rm0, fmaxf(s[nt][0], s[nt][1]));
            rm1 = fmaxf(rm1, fmaxf(s[nt][2], s[nt][3]));
        }
        rm0 = fmaxf(rm0, __shfl_xor_sync(0xffffffffu, rm0, 1));
        rm0 = fmaxf(rm0, __shfl_xor_sync(0xffffffffu, rm0, 2));
        rm1 = fmaxf(rm1, __shfl_xor_sync(0xffffffffu, rm1, 1));
        rm1 = fmaxf(rm1, __shfl_xor_sync(0xffffffffu, rm1, 2));

        float nm0 = fmaxf(m_i[0], rm0);
        float nm1 = fmaxf(m_i[1], rm1);
        float corr0 = __expf(m_i[0] - nm0);
        float corr1 = __expf(m_i[1] - nm1);
        m_i[0] = nm0; m_i[1] = nm1;

        float rs0 = 0.f, rs1 = 0.f;
        #pragma unroll
        for (int nt = 0; nt < 8; nt++) {
            s[nt][0] = __expf(s[nt][0] - nm0);
            s[nt][1] = __expf(s[nt][1] - nm0);
            s[nt][2] = __expf(s[nt][2] - nm1);
            s[nt][3] = __expf(s[nt][3] - nm1);
            rs0 += s[nt][0] + s[nt][1];
            rs1 += s[nt][2] + s[nt][3];
        }
        rs0 += __shfl_xor_sync(0xffffffffu, rs0, 1);
        rs0 += __shfl_xor_sync(0xffffffffu, rs0, 2);
        rs1 += __shfl_xor_sync(0xffffffffu, rs1, 1);
        rs1 += __shfl_xor_sync(0xffffffffu, rs1, 2);
        l_i[0] = l_i[0] * corr0 + rs0;
        l_i[1] = l_i[1] * corr1 + rs1;

        #pragma unroll
        for (int nt = 0; nt < 8; nt++) {
            o[nt][0] *= corr0; o[nt][1] *= corr0;
            o[nt][2] *= corr1; o[nt][3] *= corr1;
        }

        // Stage P as half (warp-private rows)
        #pragma unroll
        for (int nt = 0; nt < 8; nt++) {
            *reinterpret_cast<__half2*>(
                &Ps[(r0 + grp) * HStr + nt * 8 + 2 * tig]) =
                __floats2half2_rn(s[nt][0], s[nt][1]);
            *reinterpret_cast<__half2*>(
                &Ps[(r0 + grp + 8) * HStr + nt * 8 + 2 * tig]) =
                __floats2half2_rn(s[nt][2], s[nt][3]);
        }
        __syncwarp();

        // O += P V : A = P (ldsm x4), B = V via ldmatrix .trans
        #pragma unroll
        for (int kk = 0; kk < 4; kk++) {
            uint32_t af[4];
            ldsm_x4(af, sPs + pLane + (uint32_t)(kk * 16) * 2);
            const uint32_t vRow = sVs + vLane + (uint32_t)(kk * 16 * HStr) * 2;
            #pragma unroll
            for (int nt = 0; nt < 8; nt++) {
                uint32_t bf[2];
                ldsm_x2t(bf, vRow + (uint32_t)(nt * 8) * 2);
                mma_f16(o[nt], af, bf);
            }
        }
    }

    // Epilogue: normalize, write half to concat layout g_Zh[b, s, h*64+dv]
    float inv0 = 1.0f / l_i[0];
    float inv1 = 1.0f / l_i[1];
    int row0 = q0 + r0 + grp;
    #pragma unroll
    for (int nt = 0; nt < 8; nt++) {
        int col = h * 64 + nt * 8 + 2 * tig;
        *reinterpret_cast<__half2*>(
            &g_Zh[((size_t)b * Sn + row0) * 1024 + col]) =
            __floats2half2_rn(o[nt][0] * inv0, o[nt][1] * inv0);
        *reinterpret_cast<__half2*>(
            &g_Zh[((size_t)b * Sn + row0 + 8) * 1024 + col]) =
            __floats2half2_rn(o[nt][2] * inv1, o[nt][3] * inv1);
    }
}

// ---------------------------------------------------------------------------
extern "C" void kernel_launch(void* const* d_in, const int* in_sizes, int n_in,
                              void* d_out, int out_size)
{
    const float* X  = (const float*)d_in[0];
    const float* Wk = (const float*)d_in[1];
    const float* bk = (const float*)d_in[2];
    const float* Wq = (const float*)d_in[3];
    const float* bq = (const float*)d_in[4];
    const float* Wv = (const float*)d_in[5];
    const float* bv = (const float*)d_in[6];
    const float* Wo = (const float*)d_in[7];
    const float* bo = (const float*)d_in[8];
    float* out = (float*)d_out;

    cudaFuncSetAttribute(gemm_mma_kernel<0>,
                         cudaFuncAttributeMaxDynamicSharedMemorySize, GEMM_SMEM);
    cudaFuncSetAttribute(gemm_mma_kernel<1>,
                         cudaFuncAttributeMaxDynamicSharedMemorySize, GEMM_SMEM);
    cudaFuncSetAttribute(attn_mma_kernel,
                         cudaFuncAttributeMaxDynamicSharedMemorySize, ATTN_SMEM);

    x2h_kernel<<<2048, 256>>>(X);
    transpose_w_kernel<<<dim3(128, 32), 256>>>(Wq, Wk, Wv, Wo);
    gemm_mma_kernel<0><<<dim3(24, 32), 256, GEMM_SMEM>>>(
        bq, bk, bv, nullptr, nullptr);
    attn_mma_kernel<<<dim3(Sn / 128, Hn, Bn), 256, ATTN_SMEM>>>();
    gemm_mma_kernel<1><<<dim3(8, 32), 256, GEMM_SMEM>>>(
        bo, nullptr, nullptr, X, out);
}

// round 11
// speedup vs baseline: 2.0280x; 1.0629x over previous
#include <cuda_runtime.h>
#include <cuda_fp16.h>
#include <cstdint>

#define Bn  4
#define Sn  1024
#define DMn 1024
#define Hn  16
#define DKn 64

// Scratch (allocation-free rule: __device__ globals). All half.
__device__ __half g_Xh[(size_t)Bn * Sn * DMn];        // X in half
__device__ __half g_Qh[(size_t)Bn * Hn * Sn * DKn];   // pre-scaled by 0.125*log2e
__device__ __half g_Kh[(size_t)Bn * Hn * Sn * DKn];
__device__ __half g_Vh[(size_t)Bn * Hn * Sn * DKn];
__device__ __half g_Zh[(size_t)Bn * Sn * Hn * DKn];   // [b,s,h*64+v]
// K-major half weights: rows n, cols d.
//   n in [0,1024): Q | [1024,2048): K | [2048,3072): V | [3072,4096): Wo col
__device__ __half g_Wth[(size_t)4096 * 1024];

__device__ __forceinline__ uint32_t smem_u32(const void* p) {
    uint32_t a;
    asm("{ .reg .u64 t; cvta.to.shared.u64 t, %1; cvt.u32.u64 %0, t; }"
        : "=r"(a) : "l"(p));
    return a;
}
__device__ __forceinline__ void cp16(uint32_t dst, const void* src) {
    asm volatile("cp.async.cg.shared.global [%0], [%1], 16;"
                 :: "r"(dst), "l"(src));
}
__device__ __forceinline__ void cp_commit() {
    asm volatile("cp.async.commit_group;");
}
template <int N>
__device__ __forceinline__ void cp_wait() {
    asm volatile("cp.async.wait_group %0;" :: "n"(N));
}
__device__ __forceinline__ void ldsm_x4(uint32_t* r, uint32_t addr) {
    asm volatile("ldmatrix.sync.aligned.m8n8.x4.shared.b16 {%0,%1,%2,%3}, [%4];"
                 : "=r"(r[0]), "=r"(r[1]), "=r"(r[2]), "=r"(r[3]) : "r"(addr));
}
__device__ __forceinline__ void ldsm_x2(uint32_t* r, uint32_t addr) {
    asm volatile("ldmatrix.sync.aligned.m8n8.x2.shared.b16 {%0,%1}, [%2];"
                 : "=r"(r[0]), "=r"(r[1]) : "r"(addr));
}
__device__ __forceinline__ void ldsm_x2t(uint32_t* r, uint32_t addr) {
    asm volatile("ldmatrix.sync.aligned.m8n8.x2.trans.shared.b16 {%0,%1}, [%2];"
                 : "=r"(r[0]), "=r"(r[1]) : "r"(addr));
}
__device__ __forceinline__ float ex2f(float x) {
    float y;
    asm("ex2.approx.f32 %0, %1;" : "=f"(y) : "f"(x));
    return y;
}

// fp16 mma: m16n8k16, f32 accumulate.
__device__ __forceinline__ void mma_f16(float* c, const uint32_t* a, const uint32_t* b) {
    asm volatile(
        "mma.sync.aligned.m16n8k16.row.col.f32.f16.f16.f32 "
        "{%0,%1,%2,%3}, {%4,%5,%6,%7}, {%8,%9}, {%0,%1,%2,%3};"
        : "+f"(c[0]), "+f"(c[1]), "+f"(c[2]), "+f"(c[3])
        : "r"(a[0]), "r"(a[1]), "r"(a[2]), "r"(a[3]), "r"(b[0]), "r"(b[1]));
}

// ---------------------------------------------------------------------------
// Kernel 0 (fused prep): blocks [0,2048) convert X->half;
// blocks [2048,6144) transpose weights to K-major half.
// ---------------------------------------------------------------------------
__global__ __launch_bounds__(256) void prep_kernel(
    const float* __restrict__ X,
    const float* __restrict__ Wq, const float* __restrict__ Wk,
    const float* __restrict__ Wv, const float* __restrict__ Wo)
{
    int blk = blockIdx.x;
    int tid = threadIdx.x;
    if (blk < 2048) {
        size_t base = ((size_t)blk * 256 + tid) * 8;
        #pragma unroll
        for (int j = 0; j < 4; j++) {
            float2 v = *reinterpret_cast<const float2*>(&X[base + j * 2]);
            *reinterpret_cast<__half2*>(&g_Xh[base + j * 2]) =
                __floats2half2_rn(v.x, v.y);
        }
        return;
    }
    __shared__ float t[32][33];
    int bid = blk - 2048;              // 0..4095
    int bx  = bid & 127;               // n-tile
    int by  = bid >> 7;                // d-tile
    int n0 = bx * 32;
    int d0 = by * 32;
    int r  = n0 >> 10;

    #pragma unroll
    for (int p = 0; p < 4; p++) {
        int idx = p * 256 + tid;
        int dl  = idx >> 5;
        int j   = idx & 31;
        int d   = d0 + dl;
        float v;
        if (r < 3) {
            int hh = (n0 >> 6) & 15;
            int k0 = n0 & 63;
            const float* W = (r == 0) ? Wq : (r == 1) ? Wk : Wv;
            v = W[(size_t)hh * 65536 + (size_t)d * 64 + k0 + j];
        } else {
            v = Wo[(size_t)d * 1024 + (n0 - 3072) + j];
        }
        t[dl][j] = v;
    }
    __syncthreads();
    #pragma unroll
    for (int p = 0; p < 4; p++) {
        int idx = p * 256 + tid;
        int nl  = idx >> 5;
        int dd  = idx & 31;
        g_Wth[(size_t)(n0 + nl) * 1024 + d0 + dd] = __float2half_rn(t[dd][nl]);
    }
}

// ---------------------------------------------------------------------------
// fp16 mma GEMM: BM=128, BN=128, K-chunk=64 halves, 16 chunks, 3-stage ring.
// (unchanged from R10, proven)
// ---------------------------------------------------------------------------
#define HStr 72
#define GEMM_STAGE_B ((128 + 128) * HStr * 2)
#define GEMM_SMEM    (3 * GEMM_STAGE_B)

template <int MODE>
__global__ __launch_bounds__(256, 2) void gemm_mma_kernel(
    const float* __restrict__ b0, const float* __restrict__ b1,
    const float* __restrict__ b2,
    const float* __restrict__ Xres, float* __restrict__ Out)
{
    extern __shared__ __half smh[];
    const uint32_t s0 = smem_u32(smh);
    const uint32_t bHalfOff = 128 * HStr * 2;

    const int tid  = threadIdx.x;
    const int wid  = tid >> 5;
    const int lane = tid & 31;
    const int grp  = lane >> 2;
    const int tig  = lane & 3;
    const int wm   = wid & 1;
    const int wn   = wid >> 1;
    const int n0   = blockIdx.x * 128;
    const int m0   = blockIdx.y * 128;

    const __half* A  = (MODE == 0) ? g_Xh : g_Zh;
    const __half* Bw = (MODE == 0) ? g_Wth : (g_Wth + (size_t)3072 * 1024);

    const __half* srcA[4];
    const __half* srcB[4];
    uint32_t dstOff[4];
    #pragma unroll
    for (int i = 0; i < 4; i++) {
        int idx = i * 256 + tid;
        int row = idx >> 3;
        int c8  = idx & 7;
        srcA[i] = A  + (size_t)(m0 + row) * 1024 + c8 * 8;
        srcB[i] = Bw + (size_t)(n0 + row) * 1024 + c8 * 8;
        dstOff[i] = (uint32_t)(row * HStr + c8 * 8) * 2;
    }

    const int laneRowA = ((lane >> 3) & 1) * 8 + (lane & 7);
    const int laneColA = (lane >> 4) * 8;
    const int laneRowB = lane & 7;
    const int laneColB = ((lane >> 3) & 1) * 8;
    uint32_t aLane[4], bLane[4];
    #pragma unroll
    for (int mt = 0; mt < 4; mt++)
        aLane[mt] = (uint32_t)((wm * 64 + mt * 16 + laneRowA) * HStr + laneColA) * 2;
    #pragma unroll
    for (int nt = 0; nt < 4; nt++)
        bLane[nt] = (uint32_t)((wn * 32 + nt * 8 + laneRowB) * HStr + laneColB) * 2;

    float acc[4][4][4];
    #pragma unroll
    for (int mt = 0; mt < 4; mt++)
        #pragma unroll
        for (int nt = 0; nt < 4; nt++)
            #pragma unroll
            for (int e = 0; e < 4; e++) acc[mt][nt][e] = 0.f;

    #pragma unroll
    for (int st = 0; st < 2; st++) {
        uint32_t base = s0 + st * GEMM_STAGE_B;
        int kt = st * 64;
        #pragma unroll
        for (int i = 0; i < 4; i++) {
            cp16(base + dstOff[i], srcA[i] + kt);
            cp16(base + bHalfOff + dstOff[i], srcB[i] + kt);
        }
        cp_commit();
    }

    int stC = 0;
    for (int ch = 0; ch < 16; ch++) {
        if (ch < 15) cp_wait<1>(); else cp_wait<0>();
        __syncthreads();

        if (ch < 14) {
            int stN = stC + 2; if (stN >= 3) stN -= 3;
            uint32_t base = s0 + stN * GEMM_STAGE_B;
            int kt = (ch + 2) * 64;
            #pragma unroll
            for (int i = 0; i < 4; i++) {
                cp16(base + dstOff[i], srcA[i] + kt);
                cp16(base + bHalfOff + dstOff[i], srcB[i] + kt);
            }
            cp_commit();
        }

        const uint32_t sAs = s0 + stC * GEMM_STAGE_B;
        const uint32_t sBs = sAs + bHalfOff;

        #pragma unroll
        for (int ks = 0; ks < 4; ks++) {
            const uint32_t kOff = (uint32_t)(ks * 16) * 2;
            uint32_t bf[4][2];
            #pragma unroll
            for (int nt = 0; nt < 4; nt++)
                ldsm_x2(bf[nt], sBs + bLane[nt] + kOff);
            #pragma unroll
            for (int mt = 0; mt < 4; mt++) {
                uint32_t af[4];
                ldsm_x4(af, sAs + aLane[mt] + kOff);
                #pragma unroll
                for (int nt = 0; nt < 4; nt++)
                    mma_f16(acc[mt][nt], af, bf[nt]);
            }
        }
        if (++stC >= 3) stC = 0;
    }

    // Epilogue
    #pragma unroll
    for (int nt = 0; nt < 4; nt++) {
        int n_base = n0 + wn * 32 + nt * 8;
        int ncol   = 2 * tig;
        if (MODE == 0) {
            int sel = n_base >> 10;
            int hh  = (n_base >> 6) & 15;
            int kk  = (n_base & 63) + ncol;
            const float* bias = (sel == 0) ? b0 : (sel == 1) ? b1 : b2;
            __half* dst = (sel == 0) ? g_Qh : (sel == 1) ? g_Kh : g_Vh;
            // Q pre-scaled by 1/sqrt(d) * log2(e) for exp2-domain softmax
            float scale = (sel == 0) ? 0.18033688f : 1.0f;
            float bv0 = bias[hh * 64 + kk];
            float bv1 = bias[hh * 64 + kk + 1];
            #pragma unroll
            for (int mt = 0; mt < 4; mt++) {
                int r = m0 + wm * 64 + mt * 16 + grp;
                #pragma unroll
                for (int hrow = 0; hrow < 2; hrow++) {
                    int m  = r + hrow * 8;
                    int bb = m >> 10, ss = m & 1023;
                    float v0 = (acc[mt][nt][hrow * 2 + 0] + bv0) * scale;
                    float v1 = (acc[mt][nt][hrow * 2 + 1] + bv1) * scale;
                    *reinterpret_cast<__half2*>(
                        &dst[((size_t)(bb * 16 + hh) * 1024 + ss) * 64 + kk]) =
                        __floats2half2_rn(v0, v1);
                }
            }
        } else {
            int n  = n_base + ncol;
            float bv0 = b0[n], bv1 = b0[n + 1];
            #pragma unroll
            for (int mt = 0; mt < 4; mt++) {
                int r = m0 + wm * 64 + mt * 16 + grp;
                #pragma unroll
                for (int hrow = 0; hrow < 2; hrow++) {
                    int m = r + hrow * 8;
                    float2 xr = *reinterpret_cast<const float2*>(
                        &Xres[(size_t)m * 1024 + n]);
                    float2 v;
                    v.x = acc[mt][nt][hrow * 2 + 0] + bv0 + xr.x;
                    v.y = acc[mt][nt][hrow * 2 + 1] + bv1 + xr.y;
                    *reinterpret_cast<float2*>(&Out[(size_t)m * 1024 + n]) = v;
                }
            }
        }
    }
}

// ---------------------------------------------------------------------------
// Kernel 2: flash attention, fp16 mma, exp2 softmax, P kept in registers
// (C-fragment of S == A-fragment of PV; no smem round trip, no syncwarp).
// ---------------------------------------------------------------------------
#define ATTN_SMEM ((128 + 2 * 64 + 2 * 64) * HStr * 2)

__global__ __launch_bounds__(256, 2) void attn_mma_kernel()
{
    extern __shared__ __half smh[];
    __half* Ps    = smh;                       // 128 x 72 (Q staging only)
    __half* KsBuf = smh + 128 * HStr;          // 2 x 64 x 72
    __half* VsBuf = KsBuf + 2 * 64 * HStr;     // 2 x 64 x 72
    const uint32_t sPs = smem_u32(Ps);
    const uint32_t sK0 = smem_u32(KsBuf);
    const uint32_t sV0 = smem_u32(VsBuf);
    const uint32_t tileBytes = 64 * HStr * 2;

    const int q0 = blockIdx.x * 128;
    const int h  = blockIdx.y;
    const int b  = blockIdx.z;
    const int bh = b * Hn + h;

    const __half* Qg = g_Qh + (size_t)bh * Sn * DKn;
    const __half* Kg = g_Kh + (size_t)bh * Sn * DKn;
    const __half* Vg = g_Vh + (size_t)bh * Sn * DKn;

    const int tid  = threadIdx.x;
    const int wid  = tid >> 5;
    const int lane = tid & 31;
    const int r0   = wid * 16;

    const int laneRowA = ((lane >> 3) & 1) * 8 + (lane & 7);
    const int laneColA = (lane >> 4) * 8;
    const uint32_t pLane = (uint32_t)((r0 + laneRowA) * HStr + laneColA) * 2;
    uint32_t kLane[8];
    #pragma unroll
    for (int nt = 0; nt < 8; nt++)
        kLane[nt] = (uint32_t)((nt * 8 + (lane & 7)) * HStr +
                               ((lane >> 3) & 1) * 8) * 2;
    const uint32_t vLane = (uint32_t)((lane & 15) * HStr) * 2;

    const __half* srcK[2];
    const __half* srcV[2];
    uint32_t dstKV[2];
    #pragma unroll
    for (int i = 0; i < 2; i++) {
        int idx = i * 256 + tid;
        int row = idx >> 3;
        int c8  = idx & 7;
        srcK[i] = Kg + (size_t)row * DKn + c8 * 8;
        srcV[i] = Vg + (size_t)row * DKn + c8 * 8;
        dstKV[i] = (uint32_t)(row * HStr + c8 * 8) * 2;
    }
    const __half* srcQ[4];
    uint32_t dstQ[4];
    #pragma unroll
    for (int i = 0; i < 4; i++) {
        int idx = i * 256 + tid;
        int row = idx >> 3;
        int c8  = idx & 7;
        srcQ[i] = Qg + (size_t)(q0 + row) * DKn + c8 * 8;
        dstQ[i] = (uint32_t)(row * HStr + c8 * 8) * 2;
    }

    // Prologue: stage K/V tile 0 and Q
    #pragma unroll
    for (int i = 0; i < 2; i++) {
        cp16(sK0 + dstKV[i], srcK[i]);
        cp16(sV0 + dstKV[i], srcV[i]);
    }
    #pragma unroll
    for (int i = 0; i < 4; i++) cp16(sPs + dstQ[i], srcQ[i]);
    cp_commit();
    cp_wait<0>();
    __syncthreads();

    uint32_t qf[4][4];
    #pragma unroll
    for (int kk = 0; kk < 4; kk++)
        ldsm_x4(qf[kk], sPs + pLane + (uint32_t)(kk * 16) * 2);

    float m_i[2] = {-3.0e38f, -3.0e38f};
    float l_i[2] = {0.f, 0.f};
    float o[8][4];
    #pragma unroll
    for (int nt = 0; nt < 8; nt++)
        #pragma unroll
        for (int e = 0; e < 4; e++) o[nt][e] = 0.f;

    for (int ti = 0; ti < 16; ti++) {
        cp_wait<0>();
        __syncthreads();

        if (ti < 15) {
            int off = (ti + 1) * 64 * DKn;
            uint32_t boff = ((ti + 1) & 1) * tileBytes;
            #pragma unroll
            for (int i = 0; i < 2; i++) {
                cp16(sK0 + boff + dstKV[i], srcK[i] + off);
                cp16(sV0 + boff + dstKV[i], srcV[i] + off);
            }
            cp_commit();
        }

        const uint32_t sKs = sK0 + (ti & 1) * tileBytes;
        const uint32_t sVs = sV0 + (ti & 1) * tileBytes;

        // S = Q K^T (Q already scaled by 0.125*log2e → scores in log2 domain)
        float s[8][4];
        #pragma unroll
        for (int nt = 0; nt < 8; nt++)
            #pragma unroll
            for (int e = 0; e < 4; e++) s[nt][e] = 0.f;

        #pragma unroll
        for (int kk = 0; kk < 4; kk++) {
            const uint32_t kOff = (uint32_t)(kk * 16) * 2;
            #pragma unroll
            for (int nt = 0; nt < 8; nt++) {
                uint32_t bf[2];
                ldsm_x2(bf, sKs + kLane[nt] + kOff);
                mma_f16(s[nt], qf[kk], bf);
            }
        }

        // Online softmax in exp2 domain
        float rm0 = -3.0e38f, rm1 = -3.0e38f;
        #pragma unroll
        for (int nt = 0; nt < 8; nt++) {
            rm0 = fmaxf(rm0, fmaxf(s[nt][0], s[nt][1]));
            rm1 = fmaxf(rm1, fmaxf(s[nt][2], s[nt][3]));
        }
        rm0 = fmaxf(rm0, __shfl_xor_sync(0xffffffffu, rm0, 1));
        rm0 = fmaxf(rm0, __shfl_xor_sync(0xffffffffu, rm0, 2));
        rm1 = fmaxf(rm1, __shfl_xor_sync(0xffffffffu, rm1, 1));
        rm1 = fmaxf(rm1, __shfl_xor_sync(0xffffffffu, rm1, 2));

        float nm0 = fmaxf(m_i[0], rm0);
        float nm1 = fmaxf(m_i[1], rm1);
        float corr0 = ex2f(m_i[0] - nm0);
        float corr1 = ex2f(m_i[1] - nm1);
        m_i[0] = nm0; m_i[1] = nm1;

        float rs0 = 0.f, rs1 = 0.f;
        #pragma unroll
        for (int nt = 0; nt < 8; nt++) {
            s[nt][0] = ex2f(s[nt][0] - nm0);
            s[nt][1] = ex2f(s[nt][1] - nm0);
            s[nt][2] = ex2f(s[nt][2] - nm1);
            s[nt][3] = ex2f(s[nt][3] - nm1);
            rs0 += s[nt][0] + s[nt][1];
            rs1 += s[nt][2] + s[nt][3];
        }
        rs0 += __shfl_xor_sync(0xffffffffu, rs0, 1);
        rs0 += __shfl_xor_sync(0xffffffffu, rs0, 2);
        rs1 += __shfl_xor_sync(0xffffffffu, rs1, 1);
        rs1 += __shfl_xor_sync(0xffffffffu, rs1, 2);
        l_i[0] = l_i[0] * corr0 + rs0;
        l_i[1] = l_i[1] * corr1 + rs1;

        #pragma unroll
        for (int nt = 0; nt < 8; nt++) {
            o[nt][0] *= corr0; o[nt][1] *= corr0;
            o[nt][2] *= corr1; o[nt][3] *= corr1;
        }

        // O += P V. P's C-fragment layout IS the A-fragment layout:
        // af = {h2(s[2kk][0..1]), h2(s[2kk][2..3]),
        //       h2(s[2kk+1][0..1]), h2(s[2kk+1][2..3])}  -- registers only.
        #pragma unroll
        for (int kk = 0; kk < 4; kk++) {
            uint32_t af[4];
            af[0] = __uint_as_float(0), af[0] = 0;  // placeholder overwritten
            af[0] = *(uint32_t*)&af[0];
            __half2 a0 = __floats2half2_rn(s[2 * kk][0],     s[2 * kk][1]);
            __half2 a1 = __floats2half2_rn(s[2 * kk][2],     s[2 * kk][3]);
            __half2 a2 = __floats2half2_rn(s[2 * kk + 1][0], s[2 * kk + 1][1]);
            __half2 a3 = __floats2half2_rn(s[2 * kk + 1][2], s[2 * kk + 1][3]);
            af[0] = *reinterpret_cast<uint32_t*>(&a0);
            af[1] = *reinterpret_cast<uint32_t*>(&a1);
            af[2] = *reinterpret_cast<uint32_t*>(&a2);
            af[3] = *reinterpret_cast<uint32_t*>(&a3);
            const uint32_t vRow = sVs + vLane + (uint32_t)(kk * 16 * HStr) * 2;
            #pragma unroll
            for (int nt = 0; nt < 8; nt++) {
                uint32_t bf[2];
                ldsm_x2t(bf, vRow + (uint32_t)(nt * 8) * 2);
                mma_f16(o[nt], af, bf);
            }
        }
    }

    // Epilogue: normalize, write half to concat layout g_Zh[b, s, h*64+dv]
    const int grp = lane >> 2;
    const int tig = lane & 3;
    float inv0 = 1.0f / l_i[0];
    float inv1 = 1.0f / l_i[1];
    int row0 = q0 + r0 + grp;
    #pragma unroll
    for (int nt = 0; nt < 8; nt++) {
        int col = h * 64 + nt * 8 + 2 * tig;
        *reinterpret_cast<__half2*>(
            &g_Zh[((size_t)b * Sn + row0) * 1024 + col]) =
            __floats2half2_rn(o[nt][0] * inv0, o[nt][1] * inv0);
        *reinterpret_cast<__half2*>(
            &g_Zh[((size_t)b * Sn + row0 + 8) * 1024 + col]) =
            __floats2half2_rn(o[nt][2] * inv1, o[nt][3] * inv1);
    }
}

// ---------------------------------------------------------------------------
extern "C" void kernel_launch(void* const* d_in, const int* in_sizes, int n_in,
                              void* d_out, int out_size)
{
    const float* X  = (const float*)d_in[0];
    const float* Wk = (const float*)d_in[1];
    const float* bk = (const float*)d_in[2];
    const float* Wq = (const float*)d_in[3];
    const float* bq = (const float*)d_in[4];
    const float* Wv = (const float*)d_in[5];
    const float* bv = (const float*)d_in[6];
    const float* Wo = (const float*)d_in[7];
    const float* bo = (const float*)d_in[8];
    float* out = (float*)d_out;

    cudaFuncSetAttribute(gemm_mma_kernel<0>,
                         cudaFuncAttributeMaxDynamicSharedMemorySize, GEMM_SMEM);
    cudaFuncSetAttribute(gemm_mma_kernel<1>,
                         cudaFuncAttributeMaxDynamicSharedMemorySize, GEMM_SMEM);
    cudaFuncSetAttribute(attn_mma_kernel,
                         cudaFuncAttributeMaxDynamicSharedMemorySize, ATTN_SMEM);

    prep_kernel<<<6144, 256>>>(X, Wq, Wk, Wv, Wo);
    gemm_mma_kernel<0><<<dim3(24, 32), 256, GEMM_SMEM>>>(
        bq, bk, bv, nullptr, nullptr);
    attn_mma_kernel<<<dim3(Sn / 128, Hn, Bn), 256, ATTN_SMEM>>>();
    gemm_mma_kernel<1><<<dim3(8, 32), 256, GEMM_SMEM>>>(
        bo, nullptr, nullptr, X, out);
}

// round 12
// speedup vs baseline: 2.0702x; 1.0208x over previous
#include <cuda_runtime.h>
#include <cuda_fp16.h>
#include <cstdint>

#define Bn  4
#define Sn  1024
#define DMn 1024
#define Hn  16
#define DKn 64

// Scratch (allocation-free rule: __device__ globals). All half.
__device__ __half g_Xh[(size_t)Bn * Sn * DMn];        // X in half
__device__ __half g_Qh[(size_t)Bn * Hn * Sn * DKn];   // pre-scaled by 0.125*log2e
__device__ __half g_Kh[(size_t)Bn * Hn * Sn * DKn];
__device__ __half g_Vh[(size_t)Bn * Hn * Sn * DKn];
__device__ __half g_Zh[(size_t)Bn * Sn * Hn * DKn];   // [b,s,h*64+v]
// K-major half weights: rows n, cols d.
//   n in [0,1024): Q | [1024,2048): K | [2048,3072): V | [3072,4096): Wo col
__device__ __half g_Wth[(size_t)4096 * 1024];

__device__ __forceinline__ uint32_t smem_u32(const void* p) {
    uint32_t a;
    asm("{ .reg .u64 t; cvta.to.shared.u64 t, %1; cvt.u32.u64 %0, t; }"
        : "=r"(a) : "l"(p));
    return a;
}
__device__ __forceinline__ void cp16(uint32_t dst, const void* src) {
    asm volatile("cp.async.cg.shared.global [%0], [%1], 16;"
                 :: "r"(dst), "l"(src));
}
__device__ __forceinline__ void cp_commit() {
    asm volatile("cp.async.commit_group;");
}
template <int N>
__device__ __forceinline__ void cp_wait() {
    asm volatile("cp.async.wait_group %0;" :: "n"(N));
}
__device__ __forceinline__ void ldsm_x4(uint32_t* r, uint32_t addr) {
    asm volatile("ldmatrix.sync.aligned.m8n8.x4.shared.b16 {%0,%1,%2,%3}, [%4];"
                 : "=r"(r[0]), "=r"(r[1]), "=r"(r[2]), "=r"(r[3]) : "r"(addr));
}
__device__ __forceinline__ void ldsm_x4t(uint32_t* r, uint32_t addr) {
    asm volatile("ldmatrix.sync.aligned.m8n8.x4.trans.shared.b16 {%0,%1,%2,%3}, [%4];"
                 : "=r"(r[0]), "=r"(r[1]), "=r"(r[2]), "=r"(r[3]) : "r"(addr));
}
__device__ __forceinline__ float ex2f(float x) {
    float y;
    asm("ex2.approx.f32 %0, %1;" : "=f"(y) : "f"(x));
    return y;
}

// fp16 mma: m16n8k16, f32 accumulate.
__device__ __forceinline__ void mma_f16(float* c, const uint32_t* a, const uint32_t* b) {
    asm volatile(
        "mma.sync.aligned.m16n8k16.row.col.f32.f16.f16.f32 "
        "{%0,%1,%2,%3}, {%4,%5,%6,%7}, {%8,%9}, {%0,%1,%2,%3};"
        : "+f"(c[0]), "+f"(c[1]), "+f"(c[2]), "+f"(c[3])
        : "r"(a[0]), "r"(a[1]), "r"(a[2]), "r"(a[3]), "r"(b[0]), "r"(b[1]));
}

// ---------------------------------------------------------------------------
// Kernel 0 (fused prep): blocks [0,2048) convert X->half;
// blocks [2048,6144) transpose weights to K-major half.
// ---------------------------------------------------------------------------
__global__ __launch_bounds__(256) void prep_kernel(
    const float* __restrict__ X,
    const float* __restrict__ Wq, const float* __restrict__ Wk,
    const float* __restrict__ Wv, const float* __restrict__ Wo)
{
    int blk = blockIdx.x;
    int tid = threadIdx.x;
    if (blk < 2048) {
        size_t base = ((size_t)blk * 256 + tid) * 8;
        #pragma unroll
        for (int j = 0; j < 4; j++) {
            float2 v = *reinterpret_cast<const float2*>(&X[base + j * 2]);
            *reinterpret_cast<__half2*>(&g_Xh[base + j * 2]) =
                __floats2half2_rn(v.x, v.y);
        }
        return;
    }
    __shared__ float t[32][33];
    int bid = blk - 2048;
    int bx  = bid & 127;
    int by  = bid >> 7;
    int n0 = bx * 32;
    int d0 = by * 32;
    int r  = n0 >> 10;

    #pragma unroll
    for (int p = 0; p < 4; p++) {
        int idx = p * 256 + tid;
        int dl  = idx >> 5;
        int j   = idx & 31;
        int d   = d0 + dl;
        float v;
        if (r < 3) {
            int hh = (n0 >> 6) & 15;
            int k0 = n0 & 63;
            const float* W = (r == 0) ? Wq : (r == 1) ? Wk : Wv;
            v = W[(size_t)hh * 65536 + (size_t)d * 64 + k0 + j];
        } else {
            v = Wo[(size_t)d * 1024 + (n0 - 3072) + j];
        }
        t[dl][j] = v;
    }
    __syncthreads();
    #pragma unroll
    for (int p = 0; p < 4; p++) {
        int idx = p * 256 + tid;
        int nl  = idx >> 5;
        int dd  = idx & 31;
        g_Wth[(size_t)(n0 + nl) * 1024 + d0 + dd] = __float2half_rn(t[dd][nl]);
    }
}

// ---------------------------------------------------------------------------
// fp16 mma GEMM: BM=128, BN=128, K-chunk=64 halves, 16 chunks, 3-stage ring.
// B-fragments loaded PAIRED via ldmatrix.x4 (two n-octets per instruction).
// ---------------------------------------------------------------------------
#define HStr 72
#define GEMM_STAGE_B ((128 + 128) * HStr * 2)
#define GEMM_SMEM    (3 * GEMM_STAGE_B)

template <int MODE>
__global__ __launch_bounds__(256, 2) void gemm_mma_kernel(
    const float* __restrict__ b0, const float* __restrict__ b1,
    const float* __restrict__ b2,
    const float* __restrict__ Xres, float* __restrict__ Out)
{
    extern __shared__ __half smh[];
    const uint32_t s0 = smem_u32(smh);
    const uint32_t bHalfOff = 128 * HStr * 2;

    const int tid  = threadIdx.x;
    const int wid  = tid >> 5;
    const int lane = tid & 31;
    const int grp  = lane >> 2;
    const int tig  = lane & 3;
    const int wm   = wid & 1;
    const int wn   = wid >> 1;
    const int n0   = blockIdx.x * 128;
    const int m0   = blockIdx.y * 128;

    const __half* A  = (MODE == 0) ? g_Xh : g_Zh;
    const __half* Bw = (MODE == 0) ? g_Wth : (g_Wth + (size_t)3072 * 1024);

    const __half* srcA[4];
    const __half* srcB[4];
    uint32_t dstOff[4];
    #pragma unroll
    for (int i = 0; i < 4; i++) {
        int idx = i * 256 + tid;
        int row = idx >> 3;
        int c8  = idx & 7;
        srcA[i] = A  + (size_t)(m0 + row) * 1024 + c8 * 8;
        srcB[i] = Bw + (size_t)(n0 + row) * 1024 + c8 * 8;
        dstOff[i] = (uint32_t)(row * HStr + c8 * 8) * 2;
    }

    // A-frag lane address (x4): rows 0-15 of the m16 tile, two k-halves
    const int laneRowA = ((lane >> 3) & 1) * 8 + (lane & 7);
    const int laneColA = (lane >> 4) * 8;
    uint32_t aLane[4];
    #pragma unroll
    for (int mt = 0; mt < 4; mt++)
        aLane[mt] = (uint32_t)((wm * 64 + mt * 16 + laneRowA) * HStr + laneColA) * 2;
    // B-frag PAIRED lane address (x4): tiles (nt, k), (nt, k+8), (nt+1, k), (nt+1, k+8)
    //   group = lane>>3: n-block = (lane>>4)*8, k-half = ((lane>>3)&1)*8
    uint32_t bPair[2];
    #pragma unroll
    for (int np = 0; np < 2; np++)
        bPair[np] = (uint32_t)((wn * 32 + np * 16 + (lane >> 4) * 8 + (lane & 7)) * HStr
                               + ((lane >> 3) & 1) * 8) * 2;

    float acc[4][4][4];
    #pragma unroll
    for (int mt = 0; mt < 4; mt++)
        #pragma unroll
        for (int nt = 0; nt < 4; nt++)
            #pragma unroll
            for (int e = 0; e < 4; e++) acc[mt][nt][e] = 0.f;

    #pragma unroll
    for (int st = 0; st < 2; st++) {
        uint32_t base = s0 + st * GEMM_STAGE_B;
        int kt = st * 64;
        #pragma unroll
        for (int i = 0; i < 4; i++) {
            cp16(base + dstOff[i], srcA[i] + kt);
            cp16(base + bHalfOff + dstOff[i], srcB[i] + kt);
        }
        cp_commit();
    }

    int stC = 0;
    for (int ch = 0; ch < 16; ch++) {
        if (ch < 15) cp_wait<1>(); else cp_wait<0>();
        __syncthreads();

        if (ch < 14) {
            int stN = stC + 2; if (stN >= 3) stN -= 3;
            uint32_t base = s0 + stN * GEMM_STAGE_B;
            int kt = (ch + 2) * 64;
            #pragma unroll
            for (int i = 0; i < 4; i++) {
                cp16(base + dstOff[i], srcA[i] + kt);
                cp16(base + bHalfOff + dstOff[i], srcB[i] + kt);
            }
            cp_commit();
        }

        const uint32_t sAs = s0 + stC * GEMM_STAGE_B;
        const uint32_t sBs = sAs + bHalfOff;

        #pragma unroll
        for (int ks = 0; ks < 4; ks++) {
            const uint32_t kOff = (uint32_t)(ks * 16) * 2;
            uint32_t bf[4][2];
            #pragma unroll
            for (int np = 0; np < 2; np++) {
                uint32_t q[4];
                ldsm_x4(q, sBs + bPair[np] + kOff);
                bf[2 * np][0] = q[0]; bf[2 * np][1] = q[1];
                bf[2 * np + 1][0] = q[2]; bf[2 * np + 1][1] = q[3];
            }
            #pragma unroll
            for (int mt = 0; mt < 4; mt++) {
                uint32_t af[4];
                ldsm_x4(af, sAs + aLane[mt] + kOff);
                #pragma unroll
                for (int nt = 0; nt < 4; nt++)
                    mma_f16(acc[mt][nt], af, bf[nt]);
            }
        }
        if (++stC >= 3) stC = 0;
    }

    // Epilogue
    #pragma unroll
    for (int nt = 0; nt < 4; nt++) {
        int n_base = n0 + wn * 32 + nt * 8;
        int ncol   = 2 * tig;
        if (MODE == 0) {
            int sel = n_base >> 10;
            int hh  = (n_base >> 6) & 15;
            int kk  = (n_base & 63) + ncol;
            const float* bias = (sel == 0) ? b0 : (sel == 1) ? b1 : b2;
            __half* dst = (sel == 0) ? g_Qh : (sel == 1) ? g_Kh : g_Vh;
            float scale = (sel == 0) ? 0.18033688f : 1.0f;   // 0.125*log2(e)
            float bv0 = bias[hh * 64 + kk];
            float bv1 = bias[hh * 64 + kk + 1];
            #pragma unroll
            for (int mt = 0; mt < 4; mt++) {
                int r = m0 + wm * 64 + mt * 16 + grp;
                #pragma unroll
                for (int hrow = 0; hrow < 2; hrow++) {
                    int m  = r + hrow * 8;
                    int bb = m >> 10, ss = m & 1023;
                    float v0 = (acc[mt][nt][hrow * 2 + 0] + bv0) * scale;
                    float v1 = (acc[mt][nt][hrow * 2 + 1] + bv1) * scale;
                    *reinterpret_cast<__half2*>(
                        &dst[((size_t)(bb * 16 + hh) * 1024 + ss) * 64 + kk]) =
                        __floats2half2_rn(v0, v1);
                }
            }
        } else {
            int n  = n_base + ncol;
            float bv0 = b0[n], bv1 = b0[n + 1];
            #pragma unroll
            for (int mt = 0; mt < 4; mt++) {
                int r = m0 + wm * 64 + mt * 16 + grp;
                #pragma unroll
                for (int hrow = 0; hrow < 2; hrow++) {
                    int m = r + hrow * 8;
                    float2 xr = *reinterpret_cast<const float2*>(
                        &Xres[(size_t)m * 1024 + n]);
                    float2 v;
                    v.x = acc[mt][nt][hrow * 2 + 0] + bv0 + xr.x;
                    v.y = acc[mt][nt][hrow * 2 + 1] + bv1 + xr.y;
                    *reinterpret_cast<float2*>(&Out[(size_t)m * 1024 + n]) = v;
                }
            }
        }
    }
}

// ---------------------------------------------------------------------------
// Kernel 2: flash attention, fp16 mma, exp2 softmax, register-resident P,
// PAIRED ldmatrix.x4 for K and V(.trans) fragments.
// ---------------------------------------------------------------------------
#define ATTN_SMEM ((128 + 2 * 64 + 2 * 64) * HStr * 2)

__global__ __launch_bounds__(256, 2) void attn_mma_kernel()
{
    extern __shared__ __half smh[];
    __half* Ps    = smh;                       // 128 x 72 (Q staging only)
    __half* KsBuf = smh + 128 * HStr;          // 2 x 64 x 72
    __half* VsBuf = KsBuf + 2 * 64 * HStr;     // 2 x 64 x 72
    const uint32_t sPs = smem_u32(Ps);
    const uint32_t sK0 = smem_u32(KsBuf);
    const uint32_t sV0 = smem_u32(VsBuf);
    const uint32_t tileBytes = 64 * HStr * 2;

    const int q0 = blockIdx.x * 128;
    const int h  = blockIdx.y;
    const int b  = blockIdx.z;
    const int bh = b * Hn + h;

    const __half* Qg = g_Qh + (size_t)bh * Sn * DKn;
    const __half* Kg = g_Kh + (size_t)bh * Sn * DKn;
    const __half* Vg = g_Vh + (size_t)bh * Sn * DKn;

    const int tid  = threadIdx.x;
    const int wid  = tid >> 5;
    const int lane = tid & 31;
    const int r0   = wid * 16;

    const int laneRowA = ((lane >> 3) & 1) * 8 + (lane & 7);
    const int laneColA = (lane >> 4) * 8;
    const uint32_t pLane = (uint32_t)((r0 + laneRowA) * HStr + laneColA) * 2;
    // K paired B-frags: tiles (nt,k),(nt,k+8),(nt+1,k),(nt+1,k+8); nt=2*np
    uint32_t kPair[4];
    #pragma unroll
    for (int np = 0; np < 4; np++)
        kPair[np] = (uint32_t)((np * 16 + (lane >> 4) * 8 + (lane & 7)) * HStr
                               + ((lane >> 3) & 1) * 8) * 2;
    // V paired trans B-frags: tiles (k,dv),(k+8,dv),(k,dv+8),(k+8,dv+8); dv=np*16
    uint32_t vPair[4];
    #pragma unroll
    for (int np = 0; np < 4; np++)
        vPair[np] = (uint32_t)((((lane >> 3) & 1) * 8 + (lane & 7)) * HStr
                               + np * 16 + (lane >> 4) * 8) * 2;

    const __half* srcK[2];
    const __half* srcV[2];
    uint32_t dstKV[2];
    #pragma unroll
    for (int i = 0; i < 2; i++) {
        int idx = i * 256 + tid;
        int row = idx >> 3;
        int c8  = idx & 7;
        srcK[i] = Kg + (size_t)row * DKn + c8 * 8;
        srcV[i] = Vg + (size_t)row * DKn + c8 * 8;
        dstKV[i] = (uint32_t)(row * HStr + c8 * 8) * 2;
    }
    const __half* srcQ[4];
    uint32_t dstQ[4];
    #pragma unroll
    for (int i = 0; i < 4; i++) {
        int idx = i * 256 + tid;
        int row = idx >> 3;
        int c8  = idx & 7;
        srcQ[i] = Qg + (size_t)(q0 + row) * DKn + c8 * 8;
        dstQ[i] = (uint32_t)(row * HStr + c8 * 8) * 2;
    }

    // Prologue: stage K/V tile 0 and Q
    #pragma unroll
    for (int i = 0; i < 2; i++) {
        cp16(sK0 + dstKV[i], srcK[i]);
        cp16(sV0 + dstKV[i], srcV[i]);
    }
    #pragma unroll
    for (int i = 0; i < 4; i++) cp16(sPs + dstQ[i], srcQ[i]);
    cp_commit();
    cp_wait<0>();
    __syncthreads();

    uint32_t qf[4][4];
    #pragma unroll
    for (int kk = 0; kk < 4; kk++)
        ldsm_x4(qf[kk], sPs + pLane + (uint32_t)(kk * 16) * 2);

    float m_i[2] = {-3.0e38f, -3.0e38f};
    float l_i[2] = {0.f, 0.f};
    float o[8][4];
    #pragma unroll
    for (int nt = 0; nt < 8; nt++)
        #pragma unroll
        for (int e = 0; e < 4; e++) o[nt][e] = 0.f;

    for (int ti = 0; ti < 16; ti++) {
        cp_wait<0>();
        __syncthreads();

        if (ti < 15) {
            int off = (ti + 1) * 64 * DKn;
            uint32_t boff = ((ti + 1) & 1) * tileBytes;
            #pragma unroll
            for (int i = 0; i < 2; i++) {
                cp16(sK0 + boff + dstKV[i], srcK[i] + off);
                cp16(sV0 + boff + dstKV[i], srcV[i] + off);
            }
            cp_commit();
        }

        const uint32_t sKs = sK0 + (ti & 1) * tileBytes;
        const uint32_t sVs = sV0 + (ti & 1) * tileBytes;

        // S = Q K^T (scores in log2 domain; Q pre-scaled)
        float s[8][4];
        #pragma unroll
        for (int nt = 0; nt < 8; nt++)
            #pragma unroll
            for (int e = 0; e < 4; e++) s[nt][e] = 0.f;

        #pragma unroll
        for (int kk = 0; kk < 4; kk++) {
            const uint32_t kOff = (uint32_t)(kk * 16) * 2;
            #pragma unroll
            for (int np = 0; np < 4; np++) {
                uint32_t q[4];
                ldsm_x4(q, sKs + kPair[np] + kOff);
                mma_f16(s[2 * np],     qf[kk], q);      // {q0,q1}
                mma_f16(s[2 * np + 1], qf[kk], q + 2);  // {q2,q3}
            }
        }

        // Online softmax in exp2 domain
        float rm0 = -3.0e38f, rm1 = -3.0e38f;
        #pragma unroll
        for (int nt = 0; nt < 8; nt++) {
            rm0 = fmaxf(rm0, fmaxf(s[nt][0], s[nt][1]));
            rm1 = fmaxf(rm1, fmaxf(s[nt][2], s[nt][3]));
        }
        rm0 = fmaxf(rm0, __shfl_xor_sync(0xffffffffu, rm0, 1));
        rm0 = fmaxf(rm0, __shfl_xor_sync(0xffffffffu, rm0, 2));
        rm1 = fmaxf(rm1, __shfl_xor_sync(0xffffffffu, rm1, 1));
        rm1 = fmaxf(rm1, __shfl_xor_sync(0xffffffffu, rm1, 2));

        float nm0 = fmaxf(m_i[0], rm0);
        float nm1 = fmaxf(m_i[1], rm1);
        float corr0 = ex2f(m_i[0] - nm0);
        float corr1 = ex2f(m_i[1] - nm1);
        m_i[0] = nm0; m_i[1] = nm1;

        float rs0 = 0.f, rs1 = 0.f;
        #pragma unroll
        for (int nt = 0; nt < 8; nt++) {
            s[nt][0] = ex2f(s[nt][0] - nm0);
            s[nt][1] = ex2f(s[nt][1] - nm0);
            s[nt][2] = ex2f(s[nt][2] - nm1);
            s[nt][3] = ex2f(s[nt][3] - nm1);
            rs0 += s[nt][0] + s[nt][1];
            rs1 += s[nt][2] + s[nt][3];
        }
        rs0 += __shfl_xor_sync(0xffffffffu, rs0, 1);
        rs0 += __shfl_xor_sync(0xffffffffu, rs0, 2);
        rs1 += __shfl_xor_sync(0xffffffffu, rs1, 1);
        rs1 += __shfl_xor_sync(0xffffffffu, rs1, 2);
        l_i[0] = l_i[0] * corr0 + rs0;
        l_i[1] = l_i[1] * corr1 + rs1;

        #pragma unroll
        for (int nt = 0; nt < 8; nt++) {
            o[nt][0] *= corr0; o[nt][1] *= corr0;
            o[nt][2] *= corr1; o[nt][3] *= corr1;
        }

        // O += P V. P's C-fragment layout IS the A-fragment layout (registers).
        #pragma unroll
        for (int kk = 0; kk < 4; kk++) {
            __half2 a0 = __floats2half2_rn(s[2 * kk][0],     s[2 * kk][1]);
            __half2 a1 = __floats2half2_rn(s[2 * kk][2],     s[2 * kk][3]);
            __half2 a2 = __floats2half2_rn(s[2 * kk + 1][0], s[2 * kk + 1][1]);
            __half2 a3 = __floats2half2_rn(s[2 * kk + 1][2], s[2 * kk + 1][3]);
            uint32_t af[4];
            af[0] = *reinterpret_cast<uint32_t*>(&a0);
            af[1] = *reinterpret_cast<uint32_t*>(&a1);
            af[2] = *reinterpret_cast<uint32_t*>(&a2);
            af[3] = *reinterpret_cast<uint32_t*>(&a3);
            const uint32_t vBase = sVs + (uint32_t)(kk * 16 * HStr) * 2;
            #pragma unroll
            for (int np = 0; np < 4; np++) {
                uint32_t q[4];
                ldsm_x4t(q, vBase + vPair[np]);
                mma_f16(o[2 * np],     af, q);      // {q0,q1}
                mma_f16(o[2 * np + 1], af, q + 2);  // {q2,q3}
            }
        }
    }

    // Epilogue: normalize, write half to concat layout g_Zh[b, s, h*64+dv]
    const int grp = lane >> 2;
    const int tig = lane & 3;
    float inv0 = 1.0f / l_i[0];
    float inv1 = 1.0f / l_i[1];
    int row0 = q0 + r0 + grp;
    #pragma unroll
    for (int nt = 0; nt < 8; nt++) {
        int col = h * 64 + nt * 8 + 2 * tig;
        *reinterpret_cast<__half2*>(
            &g_Zh[((size_t)b * Sn + row0) * 1024 + col]) =
            __floats2half2_rn(o[nt][0] * inv0, o[nt][1] * inv0);
        *reinterpret_cast<__half2*>(
            &g_Zh[((size_t)b * Sn + row0 + 8) * 1024 + col]) =
            __floats2half2_rn(o[nt][2] * inv1, o[nt][3] * inv1);
    }
}

// ---------------------------------------------------------------------------
extern "C" void kernel_launch(void* const* d_in, const int* in_sizes, int n_in,
                              void* d_out, int out_size)
{
    const float* X  = (const float*)d_in[0];
    const float* Wk = (const float*)d_in[1];
    const float* bk = (const float*)d_in[2];
    const float* Wq = (const float*)d_in[3];
    const float* bq = (const float*)d_in[4];
    const float* Wv = (const float*)d_in[5];
    const float* bv = (const float*)d_in[6];
    const float* Wo = (const float*)d_in[7];
    const float* bo = (const float*)d_in[8];
    float* out = (float*)d_out;

    cudaFuncSetAttribute(gemm_mma_kernel<0>,
                         cudaFuncAttributeMaxDynamicSharedMemorySize, GEMM_SMEM);
    cudaFuncSetAttribute(gemm_mma_kernel<1>,
                         cudaFuncAttributeMaxDynamicSharedMemorySize, GEMM_SMEM);
    cudaFuncSetAttribute(attn_mma_kernel,
                         cudaFuncAttributeMaxDynamicSharedMemorySize, ATTN_SMEM);

    prep_kernel<<<6144, 256>>>(X, Wq, Wk, Wv, Wo);
    gemm_mma_kernel<0><<<dim3(24, 32), 256, GEMM_SMEM>>>(
        bq, bk, bv, nullptr, nullptr);
    attn_mma_kernel<<<dim3(Sn / 128, Hn, Bn), 256, ATTN_SMEM>>>();
    gemm_mma_kernel<1><<<dim3(8, 32), 256, GEMM_SMEM>>>(
        bo, nullptr, nullptr, X, out);
}